// round 1
// baseline (speedup 1.0000x reference)
#include <cuda_runtime.h>
#include <math.h>

#define NN_MAX   50000
#define HID      256
#define QKVW     768
#define E1_MAX   1600000
#define EP_MAX   500000
#define NHEAD    4

// ---------------- scratch (device globals: allocation-free) ----------------
__device__ int   g_is64;
__device__ int   g_indeg [NN_MAX];
__device__ float g_dinv  [NN_MAX];
__device__ int   g_rowptr[NN_MAX + 1];
__device__ int   g_cursor[NN_MAX];
__device__ int   g_colidx[E1_MAX];
__device__ float g_t   [(size_t)NN_MAX * HID];    // post-GEMM, pre-aggregation
__device__ float g_h   [(size_t)NN_MAX * HID];    // layer-1 output
__device__ float g_z   [(size_t)NN_MAX * HID];    // layer-2 output
__device__ float g_qkv [(size_t)NN_MAX * QKVW];   // [N,768]: Q|K|V
__device__ float g_wt  [HID * QKVW];              // in_proj_w transposed -> [256,768]
__device__ float g_wcol[HID];
__device__ float g_bsum;
__device__ float g_qkself[NN_MAX * NHEAD];
__device__ float g_vw    [NN_MAX * NHEAD];

// ---------------- helpers ----------------
__device__ __forceinline__ int edge_at(const void* p, long long i, int is64) {
    return is64 ? (int)((const long long*)p)[i] : ((const int*)p)[i];
}

// Detect whether index buffer is int64 (odd 32-bit words all zero) or int32.
__global__ void detect64_kernel(const int* __restrict__ w) {
    __shared__ int any;
    if (threadIdx.x == 0) any = 0;
    __syncthreads();
    for (int i = threadIdx.x; i < 1024; i += blockDim.x)
        if (w[2 * i + 1] != 0) any = 1;
    __syncthreads();
    if (threadIdx.x == 0) g_is64 = (any ? 0 : 1);
}

__global__ void zero_indeg_kernel(int n) {
    int i = blockIdx.x * blockDim.x + threadIdx.x;
    if (i < n) g_indeg[i] = 0;
}

__global__ void histo_kernel(const void* __restrict__ ei, int E) {
    int i = blockIdx.x * blockDim.x + threadIdx.x;
    if (i < E) {
        int d = edge_at(ei, (long long)E + i, g_is64);
        atomicAdd(&g_indeg[d], 1);
    }
}

// single-block scan: row_ptr (exclusive), cursor copy, dinv = rsqrt(indeg+1)
__global__ void scan_kernel(int n) {
    __shared__ int wsum[32];
    __shared__ int carry;
    int tid = threadIdx.x, lane = tid & 31, wid = tid >> 5;
    if (tid == 0) carry = 0;
    __syncthreads();
    for (int base = 0; base < n; base += 1024) {
        int i = base + tid;
        int v = (i < n) ? g_indeg[i] : 0;
        int x = v;
        #pragma unroll
        for (int off = 1; off < 32; off <<= 1) {
            int y = __shfl_up_sync(0xffffffffu, x, off);
            if (lane >= off) x += y;
        }
        if (lane == 31) wsum[wid] = x;
        __syncthreads();
        if (wid == 0) {
            int s = wsum[lane];
            #pragma unroll
            for (int off = 1; off < 32; off <<= 1) {
                int y = __shfl_up_sync(0xffffffffu, s, off);
                if (lane >= off) s += y;
            }
            wsum[lane] = s;
        }
        __syncthreads();
        int prev = wid ? wsum[wid - 1] : 0;
        int incl = x + prev + carry;
        if (i < n) {
            int excl = incl - v;
            g_rowptr[i] = excl;
            g_cursor[i] = excl;
            g_dinv[i]   = rsqrtf((float)(v + 1));
        }
        __syncthreads();
        if (tid == 0) carry += wsum[31];
        __syncthreads();
    }
    if (threadIdx.x == 0) g_rowptr[n] = carry;
}

__global__ void scatter_kernel(const void* __restrict__ ei, int E) {
    int i = blockIdx.x * blockDim.x + threadIdx.x;
    if (i < E) {
        int is64 = g_is64;
        int s = edge_at(ei, i, is64);
        int d = edge_at(ei, (long long)E + i, is64);
        int pos = atomicAdd(&g_cursor[d], 1);
        g_colidx[pos] = s;
    }
}

// in_proj_w [768,256] -> g_wt [256,768]
__global__ void transpose_kernel(const float* __restrict__ w) {
    int idx = blockIdx.x * blockDim.x + threadIdx.x;
    if (idx < QKVW * HID) {
        int n = idx / HID, k = idx % HID;
        g_wt[k * QKVW + n] = w[idx];
    }
}

// w_col[i] = sum_j out_proj_w[j,i]; bsum = sum(out_proj_b)
__global__ void wcol_kernel(const float* __restrict__ w, const float* __restrict__ b) {
    __shared__ float sb[HID];
    int i = threadIdx.x;
    float s = 0.f;
    for (int j = 0; j < HID; j++) s += w[j * HID + i];
    g_wcol[i] = s;
    sb[i] = b[i];
    __syncthreads();
    for (int off = HID / 2; off > 0; off >>= 1) {
        if (i < off) sb[i] += sb[i + off];
        __syncthreads();
    }
    if (i == 0) g_bsum = sb[0];
}

// ---------------- SGEMM core: C[m,n] = (A@B + bias[n]) * (SCALE? dinv[m] : 1)
// BM=128 BN=128 BK=16, 256 threads, 8x8 per thread. N,K compile-time.
template <int N, int K, bool SCALE>
__device__ __forceinline__ void sgemm_core(const float* __restrict__ A,
                                           const float* __restrict__ B,
                                           const float* __restrict__ bias,
                                           float* __restrict__ C, int M) {
    __shared__ float As[16][132];
    __shared__ float Bs[16][128];
    int tid = threadIdx.x;
    int tx = tid & 15, ty = tid >> 4;
    int bm = blockIdx.y * 128, bn = blockIdx.x * 128;
    float acc[8][8];
    #pragma unroll
    for (int i = 0; i < 8; i++)
        #pragma unroll
        for (int j = 0; j < 8; j++) acc[i][j] = 0.f;

    int aRow = tid >> 2;         // 0..63
    int aCol = (tid & 3) * 4;    // 0,4,8,12
    int bRow = tid >> 5;         // 0..7
    int bCol = (tid & 31) * 4;

    for (int k0 = 0; k0 < K; k0 += 16) {
        #pragma unroll
        for (int r = 0; r < 128; r += 64) {
            int gr = bm + aRow + r;
            float4 v = make_float4(0.f, 0.f, 0.f, 0.f);
            if (gr < M) v = *(const float4*)&A[(size_t)gr * K + k0 + aCol];
            As[aCol + 0][aRow + r] = v.x;
            As[aCol + 1][aRow + r] = v.y;
            As[aCol + 2][aRow + r] = v.z;
            As[aCol + 3][aRow + r] = v.w;
        }
        #pragma unroll
        for (int r = 0; r < 16; r += 8) {
            float4 v = *(const float4*)&B[(size_t)(k0 + bRow + r) * N + bn + bCol];
            *(float4*)&Bs[bRow + r][bCol] = v;
        }
        __syncthreads();
        #pragma unroll
        for (int kk = 0; kk < 16; kk++) {
            float a[8], b[8];
            *(float4*)&a[0] = *(const float4*)&As[kk][ty * 8];
            *(float4*)&a[4] = *(const float4*)&As[kk][ty * 8 + 4];
            *(float4*)&b[0] = *(const float4*)&Bs[kk][tx * 8];
            *(float4*)&b[4] = *(const float4*)&Bs[kk][tx * 8 + 4];
            #pragma unroll
            for (int i = 0; i < 8; i++)
                #pragma unroll
                for (int j = 0; j < 8; j++) acc[i][j] += a[i] * b[j];
        }
        __syncthreads();
    }
    #pragma unroll
    for (int i = 0; i < 8; i++) {
        int gr = bm + ty * 8 + i;
        if (gr >= M) break;
        float rs = SCALE ? g_dinv[gr] : 1.f;
        #pragma unroll
        for (int j = 0; j < 8; j += 4) {
            int gc = bn + tx * 8 + j;
            float4 bv = *(const float4*)&bias[gc];
            float4 o;
            o.x = (acc[i][j + 0] + bv.x) * rs;
            o.y = (acc[i][j + 1] + bv.y) * rs;
            o.z = (acc[i][j + 2] + bv.z) * rs;
            o.w = (acc[i][j + 3] + bv.w) * rs;
            *(float4*)&C[(size_t)gr * N + gc] = o;
        }
    }
}

__global__ void __launch_bounds__(256) gemm1_kernel(const float* __restrict__ x,
                                                    const float* __restrict__ W1,
                                                    const float* __restrict__ b1, int M) {
    sgemm_core<HID, 128, true>(x, W1, b1, g_t, M);
}
__global__ void __launch_bounds__(256) gemm2_kernel(const float* __restrict__ W2,
                                                    const float* __restrict__ b2, int M) {
    sgemm_core<HID, HID, true>(g_h, W2, b2, g_t, M);
}
__global__ void __launch_bounds__(256) gemm3_kernel(const float* __restrict__ bias, int M) {
    sgemm_core<QKVW, HID, false>(g_z, g_wt, bias, g_qkv, M);
}

// ---------------- CSR aggregation: out[n] = dinv[n]*(sum_{s->n} ts[s] + ts[n])
template <bool RELU, bool TO_H>
__global__ void agg_kernel(int n_nodes) {
    int n = blockIdx.x;
    int c = threadIdx.x;
    const float* __restrict__ ts = g_t;
    float acc = ts[(size_t)n * HID + c];   // self loop (already dinv-scaled)
    int e = g_rowptr[n], end = g_rowptr[n + 1];
    for (; e + 4 <= end; e += 4) {
        int s0 = g_colidx[e + 0];
        int s1 = g_colidx[e + 1];
        int s2 = g_colidx[e + 2];
        int s3 = g_colidx[e + 3];
        acc += ts[(size_t)s0 * HID + c];
        acc += ts[(size_t)s1 * HID + c];
        acc += ts[(size_t)s2 * HID + c];
        acc += ts[(size_t)s3 * HID + c];
    }
    for (; e < end; ++e) acc += ts[(size_t)g_colidx[e] * HID + c];
    float v = g_dinv[n] * acc;
    if (RELU) v = fmaxf(v, 0.f);
    float* out = TO_H ? g_h : g_z;
    out[(size_t)n * HID + c] = v;
    (void)n_nodes;
}

// ---------------- per-node attention precompute ----------------
// qk_self[n,h] = scale * Q[n,h]·K[n,h] ; vw[n,h] = V[n,h]·w_col[h]
__global__ void node_pre_kernel(int n_nodes) {
    int warp = (blockIdx.x * blockDim.x + threadIdx.x) >> 5;
    int lane = threadIdx.x & 31;
    if (warp >= n_nodes) return;
    const float* base = g_qkv + (size_t)warp * QKVW;
    int c0 = lane * 8;
    float4 qa = *(const float4*)(base + c0);
    float4 qb = *(const float4*)(base + c0 + 4);
    float4 ka = *(const float4*)(base + HID + c0);
    float4 kb = *(const float4*)(base + HID + c0 + 4);
    float4 va = *(const float4*)(base + 2 * HID + c0);
    float4 vb = *(const float4*)(base + 2 * HID + c0 + 4);
    float4 wa = *(const float4*)(g_wcol + c0);
    float4 wb = *(const float4*)(g_wcol + c0 + 4);
    float qk = qa.x * ka.x + qa.y * ka.y + qa.z * ka.z + qa.w * ka.w
             + qb.x * kb.x + qb.y * kb.y + qb.z * kb.z + qb.w * kb.w;
    float vv = va.x * wa.x + va.y * wa.y + va.z * wa.z + va.w * wa.w
             + vb.x * wb.x + vb.y * wb.y + vb.z * wb.z + vb.w * wb.w;
    #pragma unroll
    for (int off = 1; off < 8; off <<= 1) {
        qk += __shfl_xor_sync(0xffffffffu, qk, off);
        vv += __shfl_xor_sync(0xffffffffu, vv, off);
    }
    if ((lane & 7) == 0) {
        int h = lane >> 3;
        g_qkself[warp * NHEAD + h] = 0.125f * qk;  // 1/sqrt(64)
        g_vw[warp * NHEAD + h] = vv;
    }
}

// ---------------- per-edge attention + sigmoid ----------------
__global__ void edge_attn_kernel(const void* __restrict__ eip, float* __restrict__ out, int Ep) {
    int gw = (blockIdx.x * blockDim.x + threadIdx.x) >> 5;
    int lane = threadIdx.x & 31;
    if (gw >= Ep) return;
    int is64 = g_is64;
    int sp = edge_at(eip, gw, is64);
    int dp = edge_at(eip, (long long)Ep + gw, is64);
    const float* q = g_qkv + (size_t)sp * QKVW;            // Q[sp]
    const float* k = g_qkv + (size_t)dp * QKVW + HID;      // K[dp]
    int c0 = lane * 8;
    float4 qa = *(const float4*)(q + c0);
    float4 qb = *(const float4*)(q + c0 + 4);
    float4 ka = *(const float4*)(k + c0);
    float4 kb = *(const float4*)(k + c0 + 4);
    float s = qa.x * ka.x + qa.y * ka.y + qa.z * ka.z + qa.w * ka.w
            + qb.x * kb.x + qb.y * kb.y + qb.z * kb.z + qb.w * kb.w;
    #pragma unroll
    for (int off = 1; off < 8; off <<= 1) s += __shfl_xor_sync(0xffffffffu, s, off);
    int h = lane >> 3;
    float s1 = 0.125f * s;                 // q0·k(dp) * scale
    float s0 = g_qkself[sp * NHEAD + h];   // q0·k(sp) * scale
    float m = fmaxf(s0, s1);
    float e0 = expf(s0 - m), e1 = expf(s1 - m);
    float w = (e0 * g_vw[sp * NHEAD + h] + e1 * g_vw[dp * NHEAD + h]) / (e0 + e1);
    w += __shfl_xor_sync(0xffffffffu, w, 8);
    w += __shfl_xor_sync(0xffffffffu, w, 16);
    if (lane == 0) {
        float xl = w + g_bsum;
        out[gw] = 1.f / (1.f + expf(-xl));
    }
}

// ---------------- launch ----------------
extern "C" void kernel_launch(void* const* d_in, const int* in_sizes, int n_in,
                              void* d_out, int out_size) {
    const float* x   = (const float*)d_in[0];
    const void*  ei  = d_in[1];
    const void*  eip = d_in[2];
    const float* W1  = (const float*)d_in[3];
    const float* b1  = (const float*)d_in[4];
    const float* W2  = (const float*)d_in[5];
    const float* b2  = (const float*)d_in[6];
    const float* ipw = (const float*)d_in[7];
    const float* ipb = (const float*)d_in[8];
    const float* opw = (const float*)d_in[9];
    const float* opb = (const float*)d_in[10];

    int N  = in_sizes[0] / 128;   // IN_CH = 128
    int E  = in_sizes[1] / 2;
    int Ep = in_sizes[2] / 2;
    float* out = (float*)d_out;
    (void)n_in; (void)out_size;

    // --- index dtype detection + CSR build (shared by both GCN layers) ---
    detect64_kernel<<<1, 256>>>((const int*)ei);
    zero_indeg_kernel<<<(N + 255) / 256, 256>>>(N);
    histo_kernel<<<(E + 255) / 256, 256>>>(ei, E);
    scan_kernel<<<1, 1024>>>(N);
    scatter_kernel<<<(E + 255) / 256, 256>>>(ei, E);

    // --- weight preprocessing (independent of graph) ---
    transpose_kernel<<<(QKVW * HID + 255) / 256, 256>>>(ipw);
    wcol_kernel<<<1, HID>>>(opw, opb);

    dim3 g1(HID / 128, (N + 127) / 128);
    dim3 g3(QKVW / 128, (N + 127) / 128);

    // --- layer 1: t = (x@W1+b1)*dinv ; h = relu(dinv * (gather-sum + self)) ---
    gemm1_kernel<<<g1, 256>>>(x, W1, b1, N);
    agg_kernel<true, true><<<N, HID>>>(N);

    // --- layer 2 ---
    gemm2_kernel<<<g1, 256>>>(W2, b2, N);
    agg_kernel<false, false><<<N, HID>>>(N);

    // --- per-node QKV + attention precompute ---
    gemm3_kernel<<<g3, 256>>>(ipb, N);
    node_pre_kernel<<<(N * 32 + 255) / 256, 256>>>(N);

    // --- per-edge attention + sigmoid ---
    edge_attn_kernel<<<(Ep + 7) / 8, 256>>>(eip, out, Ep);
}

// round 7
// speedup vs baseline: 1.1056x; 1.1056x over previous
#include <cuda_runtime.h>
#include <math.h>

#define NN_MAX   50000
#define HID      256
#define QKW      512
#define E1_MAX   1600000
#define EP_MAX   500000
#define NHEAD    4

// ---------------- scratch (device globals: allocation-free) ----------------
__device__ int   g_is64;
__device__ int   g_indeg [NN_MAX];
__device__ float g_dinv  [NN_MAX];
__device__ int   g_rowptr[NN_MAX + 1];
__device__ int   g_cursor[NN_MAX];
__device__ int   g_colidx[E1_MAX];
__device__ float g_t   [(size_t)NN_MAX * HID];    // post-GEMM, pre-aggregation
__device__ float g_h   [(size_t)NN_MAX * HID];    // layer-1 output
__device__ float g_z   [(size_t)NN_MAX * HID];    // layer-2 output
__device__ float g_qk  [(size_t)NN_MAX * QKW];    // [N,512]: Q|K
__device__ float g_wt  [HID * QKW];               // in_proj_w rows 0..511 transposed -> [256,512]
__device__ float g_wcol[HID];
__device__ float g_wveff[NHEAD][HID];
__device__ float g_vb[NHEAD];
__device__ float g_bsum;
__device__ float g_qkself[NN_MAX * NHEAD];
__device__ float g_vw    [NN_MAX * NHEAD];

// ---------------- helpers ----------------
__device__ __forceinline__ int edge_at(const void* p, long long i, int is64) {
    return is64 ? (int)((const long long*)p)[i] : ((const int*)p)[i];
}

// Detect whether index buffer is int64 (odd 32-bit words all zero) or int32.
__global__ void detect64_kernel(const int* __restrict__ w) {
    __shared__ int any;
    if (threadIdx.x == 0) any = 0;
    __syncthreads();
    for (int i = threadIdx.x; i < 1024; i += blockDim.x)
        if (w[2 * i + 1] != 0) any = 1;
    __syncthreads();
    if (threadIdx.x == 0) g_is64 = (any ? 0 : 1);
}

__global__ void zero_indeg_kernel(int n) {
    int i = blockIdx.x * blockDim.x + threadIdx.x;
    if (i < n) g_indeg[i] = 0;
}

__global__ void histo_kernel(const void* __restrict__ ei, int E) {
    int i = blockIdx.x * blockDim.x + threadIdx.x;
    if (i < E) {
        int d = edge_at(ei, (long long)E + i, g_is64);
        atomicAdd(&g_indeg[d], 1);
    }
}

// single-block scan: row_ptr (exclusive), cursor copy, dinv = rsqrt(indeg+1)
__global__ void scan_kernel(int n) {
    __shared__ int wsum[32];
    __shared__ int carry;
    int tid = threadIdx.x, lane = tid & 31, wid = tid >> 5;
    if (tid == 0) carry = 0;
    __syncthreads();
    for (int base = 0; base < n; base += 1024) {
        int i = base + tid;
        int v = (i < n) ? g_indeg[i] : 0;
        int x = v;
        #pragma unroll
        for (int off = 1; off < 32; off <<= 1) {
            int y = __shfl_up_sync(0xffffffffu, x, off);
            if (lane >= off) x += y;
        }
        if (lane == 31) wsum[wid] = x;
        __syncthreads();
        if (wid == 0) {
            int s = wsum[lane];
            #pragma unroll
            for (int off = 1; off < 32; off <<= 1) {
                int y = __shfl_up_sync(0xffffffffu, s, off);
                if (lane >= off) s += y;
            }
            wsum[lane] = s;
        }
        __syncthreads();
        int prev = wid ? wsum[wid - 1] : 0;
        int incl = x + prev + carry;
        if (i < n) {
            int excl = incl - v;
            g_rowptr[i] = excl;
            g_cursor[i] = excl;
            g_dinv[i]   = rsqrtf((float)(v + 1));
        }
        __syncthreads();
        if (tid == 0) carry += wsum[31];
        __syncthreads();
    }
    if (threadIdx.x == 0) g_rowptr[n] = carry;
}

__global__ void scatter_kernel(const void* __restrict__ ei, int E) {
    int i = blockIdx.x * blockDim.x + threadIdx.x;
    if (i < E) {
        int is64 = g_is64;
        int s = edge_at(ei, i, is64);
        int d = edge_at(ei, (long long)E + i, is64);
        int pos = atomicAdd(&g_cursor[d], 1);
        g_colidx[pos] = s;
    }
}

// in_proj_w rows 0..511 [512,256] -> g_wt [256,512]
__global__ void transpose_kernel(const float* __restrict__ w) {
    int idx = blockIdx.x * blockDim.x + threadIdx.x;
    if (idx < QKW * HID) {
        int n = idx / HID, k = idx % HID;
        g_wt[k * QKW + n] = w[idx];
    }
}

// w_col[i] = sum_j out_proj_w[j,i]; bsum = sum(out_proj_b)
__global__ void wcol_kernel(const float* __restrict__ w, const float* __restrict__ b) {
    __shared__ float sb[HID];
    int i = threadIdx.x;
    float s = 0.f;
    for (int j = 0; j < HID; j++) s += w[j * HID + i];
    g_wcol[i] = s;
    sb[i] = b[i];
    __syncthreads();
    for (int off = HID / 2; off > 0; off >>= 1) {
        if (i < off) sb[i] += sb[i + off];
        __syncthreads();
    }
    if (i == 0) g_bsum = sb[0];
}

// wv_eff[h][k] = sum_{i<64} ipw[512+64h+i][k] * wcol[64h+i]; vb[h] = sum_i ipb[512+64h+i]*wcol[64h+i]
__global__ void prep_wv_kernel(const float* __restrict__ ipw, const float* __restrict__ ipb) {
    __shared__ float sb[HID];
    int h = blockIdx.x, t = threadIdx.x;
    float acc = 0.f;
    for (int i = 0; i < 64; i++)
        acc += ipw[(size_t)(512 + 64 * h + i) * HID + t] * g_wcol[64 * h + i];
    g_wveff[h][t] = acc;
    sb[t] = (t < 64) ? (ipb[512 + 64 * h + t] * g_wcol[64 * h + t]) : 0.f;
    __syncthreads();
    for (int off = HID / 2; off > 0; off >>= 1) {
        if (t < off) sb[t] += sb[t + off];
        __syncthreads();
    }
    if (t == 0) g_vb[h] = sb[0];
}

// ---------------- SGEMM core: C[m,n] = (A@B + bias[n]) * (SCALE? dinv[m] : 1)
// BM=128 BN=128 BK=16, 256 threads, 8x8 per thread. N,K compile-time.
template <int N, int K, bool SCALE>
__device__ __forceinline__ void sgemm_core(const float* __restrict__ A,
                                           const float* __restrict__ B,
                                           const float* __restrict__ bias,
                                           float* __restrict__ C, int M) {
    __shared__ float As[16][132];
    __shared__ float Bs[16][128];
    int tid = threadIdx.x;
    int tx = tid & 15, ty = tid >> 4;
    int bm = blockIdx.y * 128, bn = blockIdx.x * 128;
    float acc[8][8];
    #pragma unroll
    for (int i = 0; i < 8; i++)
        #pragma unroll
        for (int j = 0; j < 8; j++) acc[i][j] = 0.f;

    int aRow = tid >> 2;         // 0..63
    int aCol = (tid & 3) * 4;    // 0,4,8,12
    int bRow = tid >> 5;         // 0..7
    int bCol = (tid & 31) * 4;

    for (int k0 = 0; k0 < K; k0 += 16) {
        #pragma unroll
        for (int r = 0; r < 128; r += 64) {
            int gr = bm + aRow + r;
            float4 v = make_float4(0.f, 0.f, 0.f, 0.f);
            if (gr < M) v = *(const float4*)&A[(size_t)gr * K + k0 + aCol];
            As[aCol + 0][aRow + r] = v.x;
            As[aCol + 1][aRow + r] = v.y;
            As[aCol + 2][aRow + r] = v.z;
            As[aCol + 3][aRow + r] = v.w;
        }
        #pragma unroll
        for (int r = 0; r < 16; r += 8) {
            float4 v = *(const float4*)&B[(size_t)(k0 + bRow + r) * N + bn + bCol];
            *(float4*)&Bs[bRow + r][bCol] = v;
        }
        __syncthreads();
        #pragma unroll
        for (int kk = 0; kk < 16; kk++) {
            float a[8], b[8];
            *(float4*)&a[0] = *(const float4*)&As[kk][ty * 8];
            *(float4*)&a[4] = *(const float4*)&As[kk][ty * 8 + 4];
            *(float4*)&b[0] = *(const float4*)&Bs[kk][tx * 8];
            *(float4*)&b[4] = *(const float4*)&Bs[kk][tx * 8 + 4];
            #pragma unroll
            for (int i = 0; i < 8; i++)
                #pragma unroll
                for (int j = 0; j < 8; j++) acc[i][j] += a[i] * b[j];
        }
        __syncthreads();
    }
    #pragma unroll
    for (int i = 0; i < 8; i++) {
        int gr = bm + ty * 8 + i;
        if (gr >= M) break;
        float rs = SCALE ? g_dinv[gr] : 1.f;
        #pragma unroll
        for (int j = 0; j < 8; j += 4) {
            int gc = bn + tx * 8 + j;
            float4 bv = *(const float4*)&bias[gc];
            float4 o;
            o.x = (acc[i][j + 0] + bv.x) * rs;
            o.y = (acc[i][j + 1] + bv.y) * rs;
            o.z = (acc[i][j + 2] + bv.z) * rs;
            o.w = (acc[i][j + 3] + bv.w) * rs;
            *(float4*)&C[(size_t)gr * N + gc] = o;
        }
    }
}

__global__ void __launch_bounds__(256) gemm1_kernel(const float* __restrict__ x,
                                                    const float* __restrict__ W1,
                                                    const float* __restrict__ b1, int M) {
    sgemm_core<HID, 128, true>(x, W1, b1, g_t, M);
}
__global__ void __launch_bounds__(256) gemm2_kernel(const float* __restrict__ W2,
                                                    const float* __restrict__ b2, int M) {
    sgemm_core<HID, HID, true>(g_h, W2, b2, g_t, M);
}
__global__ void __launch_bounds__(256) gemm3_kernel(const float* __restrict__ bias, int M) {
    sgemm_core<QKW, HID, false>(g_z, g_wt, bias, g_qk, M);
}

// ---------------- CSR aggregation: out[n] = dinv[n]*(sum_{s->n} ts[s] + ts[n])
template <bool RELU, bool TO_H>
__global__ void agg_kernel(int n_nodes) {
    int n = blockIdx.x;
    int c = threadIdx.x;
    const float* __restrict__ ts = g_t;
    float acc = ts[(size_t)n * HID + c];   // self loop (already dinv-scaled)
    int e = g_rowptr[n], end = g_rowptr[n + 1];
    for (; e + 4 <= end; e += 4) {
        int s0 = g_colidx[e + 0];
        int s1 = g_colidx[e + 1];
        int s2 = g_colidx[e + 2];
        int s3 = g_colidx[e + 3];
        acc += ts[(size_t)s0 * HID + c];
        acc += ts[(size_t)s1 * HID + c];
        acc += ts[(size_t)s2 * HID + c];
        acc += ts[(size_t)s3 * HID + c];
    }
    for (; e < end; ++e) acc += ts[(size_t)g_colidx[e] * HID + c];
    float v = g_dinv[n] * acc;
    if (RELU) v = fmaxf(v, 0.f);
    float* out = TO_H ? g_h : g_z;
    out[(size_t)n * HID + c] = v;
    (void)n_nodes;
}

// ---------------- per-node attention precompute ----------------
// qk_self[n,h] = scale * Q[n,h]·K[n,h] ; vw[n,h] = z[n]·wv_eff[h] + vb[h]
__global__ void node_pre_kernel(int n_nodes) {
    int w = (blockIdx.x * blockDim.x + threadIdx.x) >> 5;
    int lane = threadIdx.x & 31;
    if (w >= n_nodes) return;
    const float* qk = g_qk + (size_t)w * QKW;
    const float* z  = g_z  + (size_t)w * HID;
    int c0 = lane * 8;
    float4 qa = *(const float4*)(qk + c0);
    float4 qb = *(const float4*)(qk + c0 + 4);
    float4 ka = *(const float4*)(qk + 256 + c0);
    float4 kb = *(const float4*)(qk + 256 + c0 + 4);
    float4 za = *(const float4*)(z + c0);
    float4 zb = *(const float4*)(z + c0 + 4);
    float dqk = qa.x * ka.x + qa.y * ka.y + qa.z * ka.z + qa.w * ka.w
              + qb.x * kb.x + qb.y * kb.y + qb.z * kb.z + qb.w * kb.w;
    #pragma unroll
    for (int off = 1; off < 8; off <<= 1)
        dqk += __shfl_xor_sync(0xffffffffu, dqk, off);
    if ((lane & 7) == 0)
        g_qkself[w * NHEAD + (lane >> 3)] = 0.125f * dqk;  // 1/sqrt(64)

    float4 wa0 = *(const float4*)(&g_wveff[0][c0]);
    float4 wb0 = *(const float4*)(&g_wveff[0][c0 + 4]);
    float p0 = za.x * wa0.x + za.y * wa0.y + za.z * wa0.z + za.w * wa0.w
             + zb.x * wb0.x + zb.y * wb0.y + zb.z * wb0.z + zb.w * wb0.w;
    float4 wa1 = *(const float4*)(&g_wveff[1][c0]);
    float4 wb1 = *(const float4*)(&g_wveff[1][c0 + 4]);
    float p1 = za.x * wa1.x + za.y * wa1.y + za.z * wa1.z + za.w * wa1.w
             + zb.x * wb1.x + zb.y * wb1.y + zb.z * wb1.z + zb.w * wb1.w;
    float4 wa2 = *(const float4*)(&g_wveff[2][c0]);
    float4 wb2 = *(const float4*)(&g_wveff[2][c0 + 4]);
    float p2 = za.x * wa2.x + za.y * wa2.y + za.z * wa2.z + za.w * wa2.w
             + zb.x * wb2.x + zb.y * wb2.y + zb.z * wb2.z + zb.w * wb2.w;
    float4 wa3 = *(const float4*)(&g_wveff[3][c0]);
    float4 wb3 = *(const float4*)(&g_wveff[3][c0 + 4]);
    float p3 = za.x * wa3.x + za.y * wa3.y + za.z * wa3.z + za.w * wa3.w
             + zb.x * wb3.x + zb.y * wb3.y + zb.z * wb3.z + zb.w * wb3.w;
    #pragma unroll
    for (int off = 1; off < 32; off <<= 1) {
        p0 += __shfl_xor_sync(0xffffffffu, p0, off);
        p1 += __shfl_xor_sync(0xffffffffu, p1, off);
        p2 += __shfl_xor_sync(0xffffffffu, p2, off);
        p3 += __shfl_xor_sync(0xffffffffu, p3, off);
    }
    if (lane == 0) {
        g_vw[w * NHEAD + 0] = p0 + g_vb[0];
        g_vw[w * NHEAD + 1] = p1 + g_vb[1];
        g_vw[w * NHEAD + 2] = p2 + g_vb[2];
        g_vw[w * NHEAD + 3] = p3 + g_vb[3];
    }
}

// ---------------- per-edge attention + sigmoid ----------------
__global__ void edge_attn_kernel(const void* __restrict__ eip, float* __restrict__ out, int Ep) {
    int gw = (blockIdx.x * blockDim.x + threadIdx.x) >> 5;
    int lane = threadIdx.x & 31;
    if (gw >= Ep) return;
    int is64 = g_is64;
    int sp = edge_at(eip, gw, is64);
    int dp = edge_at(eip, (long long)Ep + gw, is64);
    const float* q = g_qk + (size_t)sp * QKW;            // Q[sp]
    const float* k = g_qk + (size_t)dp * QKW + 256;      // K[dp]
    int c0 = lane * 8;
    float4 qa = *(const float4*)(q + c0);
    float4 qb = *(const float4*)(q + c0 + 4);
    float4 ka = *(const float4*)(k + c0);
    float4 kb = *(const float4*)(k + c0 + 4);
    float s = qa.x * ka.x + qa.y * ka.y + qa.z * ka.z + qa.w * ka.w
            + qb.x * kb.x + qb.y * kb.y + qb.z * kb.z + qb.w * kb.w;
    #pragma unroll
    for (int off = 1; off < 8; off <<= 1) s += __shfl_xor_sync(0xffffffffu, s, off);
    int h = lane >> 3;
    float s1 = 0.125f * s;                 // q0·k(dp) * scale
    float s0 = g_qkself[sp * NHEAD + h];   // q0·k(sp) * scale
    float m = fmaxf(s0, s1);
    float e0 = expf(s0 - m), e1 = expf(s1 - m);
    float w = (e0 * g_vw[sp * NHEAD + h] + e1 * g_vw[dp * NHEAD + h]) / (e0 + e1);
    w += __shfl_xor_sync(0xffffffffu, w, 8);
    w += __shfl_xor_sync(0xffffffffu, w, 16);
    if (lane == 0) {
        float xl = w + g_bsum;
        out[gw] = 1.f / (1.f + expf(-xl));
    }
}

// ---------------- launch ----------------
extern "C" void kernel_launch(void* const* d_in, const int* in_sizes, int n_in,
                              void* d_out, int out_size) {
    const float* x   = (const float*)d_in[0];
    const void*  ei  = d_in[1];
    const void*  eip = d_in[2];
    const float* W1  = (const float*)d_in[3];
    const float* b1  = (const float*)d_in[4];
    const float* W2  = (const float*)d_in[5];
    const float* b2  = (const float*)d_in[6];
    const float* ipw = (const float*)d_in[7];
    const float* ipb = (const float*)d_in[8];
    const float* opw = (const float*)d_in[9];
    const float* opb = (const float*)d_in[10];

    int N  = in_sizes[0] / 128;   // IN_CH = 128
    int E  = in_sizes[1] / 2;
    int Ep = in_sizes[2] / 2;
    float* out = (float*)d_out;
    (void)n_in; (void)out_size;

    // --- index dtype detection + CSR build (shared by both GCN layers) ---
    detect64_kernel<<<1, 256>>>((const int*)ei);
    zero_indeg_kernel<<<(N + 255) / 256, 256>>>(N);
    histo_kernel<<<(E + 255) / 256, 256>>>(ei, E);
    scan_kernel<<<1, 1024>>>(N);
    scatter_kernel<<<(E + 255) / 256, 256>>>(ei, E);

    // --- weight preprocessing (independent of graph) ---
    transpose_kernel<<<(QKW * HID + 255) / 256, 256>>>(ipw);
    wcol_kernel<<<1, HID>>>(opw, opb);
    prep_wv_kernel<<<NHEAD, HID>>>(ipw, ipb);

    dim3 g1(HID / 128, (N + 127) / 128);
    dim3 g3(QKW / 128, (N + 127) / 128);

    // --- layer 1: t = (x@W1+b1)*dinv ; h = relu(dinv * (gather-sum + self)) ---
    gemm1_kernel<<<g1, 256>>>(x, W1, b1, N);
    agg_kernel<true, true><<<N, HID>>>(N);

    // --- layer 2 ---
    gemm2_kernel<<<g1, 256>>>(W2, b2, N);
    agg_kernel<false, false><<<N, HID>>>(N);

    // --- QK projection (V folded into wv_eff) + per-node precompute ---
    gemm3_kernel<<<g3, 256>>>(ipb, N);
    node_pre_kernel<<<(N * 32 + 255) / 256, 256>>>(N);

    // --- per-edge attention + sigmoid ---
    edge_attn_kernel<<<(Ep + 7) / 8, 256>>>(eip, out, Ep);
}